// round 2
// baseline (speedup 1.0000x reference)
#include <cuda_runtime.h>

#define SS 2048
#define MM 1024
#define HH 2048
#define EE 64
#define GG 4
// capacity C = 64 folds into a scalar factor in the final combine

// Scratch (device globals; allocation-free)
__device__ float g_gates[GG * SS * EE];          // [row][e], row = g*S+s      (2 MB)
__device__ float g_Dpart[4 * EE * GG * MM];      // [sc][e][g][m] split-K partials (4 MB)
__device__ float g_Hh[EE * GG * HH];             // [e][g][h], post-ReLU       (2 MB)
__device__ float g_O[EE * GG * MM];              // [e][g][m]                  (1 MB)

// ---------------------------------------------------------------------------
// K1: gates[row][e] = sum_m x[row][m] * wg[m][e]
// grid 1024 blocks x 256 thr; block = 8 rows, thread = (e, 2 rows)
// ---------------------------------------------------------------------------
__global__ __launch_bounds__(256) void k1_gates(const float* __restrict__ x,
                                                const float* __restrict__ wg) {
    __shared__ float xs[8 * MM];  // 32 KB
    int row0 = blockIdx.x * 8;
    const float4* x4 = (const float4*)(x + (size_t)row0 * MM);
    float4* xs4 = (float4*)xs;
    for (int i = threadIdx.x; i < 8 * MM / 4; i += 256) xs4[i] = x4[i];
    __syncthreads();

    int e = threadIdx.x & 63;
    int rq = threadIdx.x >> 6;  // 0..3  (rows rq and rq+4)
    float acc0 = 0.f, acc1 = 0.f;
#pragma unroll 8
    for (int m = 0; m < MM; m++) {
        float w = __ldg(wg + m * EE + e);
        acc0 += xs[rq * MM + m] * w;
        acc1 += xs[(rq + 4) * MM + m] * w;
    }
    g_gates[(row0 + rq) * EE + e] = acc0;
    g_gates[(row0 + rq + 4) * EE + e] = acc1;
}

// ---------------------------------------------------------------------------
// K2: Dpart[sc][e][g][m] = sum_{s in chunk sc} gates[g,s,e] * x[g,s,m]
// grid (16 m-tiles, 4 g, 4 s-chunks) x 256 thr; thread = 4e x 4m register tile
// ---------------------------------------------------------------------------
__global__ __launch_bounds__(256) void k2_dispatch(const float* __restrict__ x) {
    __shared__ float gs[64 * 64];   // [s][e] 16 KB
    __shared__ float xsm[64 * 64];  // [s][m] 16 KB
    int m0 = blockIdx.x * 64;
    int g  = blockIdx.y;
    int sc = blockIdx.z;
    int tx = threadIdx.x & 15;   // m group (4 wide)
    int ty = threadIdx.x >> 4;   // e group (4 wide)

    float acc[4][4] = {};
    for (int s0 = sc * 512; s0 < sc * 512 + 512; s0 += 64) {
        __syncthreads();
        for (int i = threadIdx.x; i < 64 * 16; i += 256) {  // 64 rows x 16 float4
            int ss = i >> 4, c = i & 15;
            ((float4*)gs)[ss * 16 + c] =
                ((const float4*)(g_gates + (size_t)(g * SS + s0 + ss) * EE))[c];
            ((float4*)xsm)[ss * 16 + c] =
                ((const float4*)(x + (size_t)(g * SS + s0 + ss) * MM + m0))[c];
        }
        __syncthreads();
#pragma unroll 8
        for (int ss = 0; ss < 64; ss++) {
            float ge[4], xv[4];
#pragma unroll
            for (int j = 0; j < 4; j++) ge[j] = gs[ss * 64 + ty * 4 + j];
#pragma unroll
            for (int j = 0; j < 4; j++) xv[j] = xsm[ss * 64 + tx * 4 + j];
#pragma unroll
            for (int ii = 0; ii < 4; ii++)
#pragma unroll
                for (int jj = 0; jj < 4; jj++) acc[ii][jj] += ge[ii] * xv[jj];
        }
    }
#pragma unroll
    for (int ii = 0; ii < 4; ii++) {
        int ee = ty * 4 + ii;
        float4 v = make_float4(acc[ii][0], acc[ii][1], acc[ii][2], acc[ii][3]);
        *((float4*)(g_Dpart + (((sc * EE + ee) * GG + g) * MM + m0 + tx * 4))) = v;
    }
}

// ---------------------------------------------------------------------------
// K3: Hh[e][g][h] = relu( sum_m D[e,g,m] * wi[e][m][h] )   -- streams wi (512 MB)
// grid (64 e, 4 h-blocks of 512) x 128 thr; thread = 4 h (float4), 4 g accums
// D assembled from the 4 split-K partials at SMEM-fill time (deterministic).
// ---------------------------------------------------------------------------
__global__ __launch_bounds__(128) void k3_ffn1(const float* __restrict__ wi) {
    __shared__ float ds[GG * MM];  // [g][m] 16 KB
    int e = blockIdx.x;
    int h0 = blockIdx.y * 512 + threadIdx.x * 4;

    const float4* dp4 = (const float4*)g_Dpart;
    for (int i = threadIdx.x; i < GG * MM / 4; i += 128) {
        float4 a = dp4[(0 * EE + e) * 1024 + i];
        float4 b = dp4[(1 * EE + e) * 1024 + i];
        float4 c = dp4[(2 * EE + e) * 1024 + i];
        float4 d = dp4[(3 * EE + e) * 1024 + i];
        ((float4*)ds)[i] = make_float4(a.x + b.x + c.x + d.x, a.y + b.y + c.y + d.y,
                                       a.z + b.z + c.z + d.z, a.w + b.w + c.w + d.w);
    }
    __syncthreads();

    float acc[4][4] = {};
    const float4* w4 = (const float4*)(wi + (size_t)e * MM * HH);
#pragma unroll 8
    for (int m = 0; m < MM; m++) {
        float4 w = w4[(m * HH + h0) >> 2];
#pragma unroll
        for (int gg = 0; gg < 4; gg++) {
            float d = ds[gg * MM + m];
            acc[gg][0] += d * w.x;
            acc[gg][1] += d * w.y;
            acc[gg][2] += d * w.z;
            acc[gg][3] += d * w.w;
        }
    }
#pragma unroll
    for (int gg = 0; gg < 4; gg++) {
        float4 v = make_float4(fmaxf(acc[gg][0], 0.f), fmaxf(acc[gg][1], 0.f),
                               fmaxf(acc[gg][2], 0.f), fmaxf(acc[gg][3], 0.f));
        *((float4*)(g_Hh + ((size_t)(e * GG + gg) * HH + h0))) = v;
    }
}

// ---------------------------------------------------------------------------
// K4: O[e][g][m] = sum_h Hh[e,g,h] * wo[e][h][m]   -- streams wo (512 MB)
// grid (64 e, 4 m-blocks of 256) x 64 thr; thread = 4 m (float4), 4 g accums
// ---------------------------------------------------------------------------
__global__ __launch_bounds__(64) void k4_ffn2(const float* __restrict__ wo) {
    __shared__ float hs[GG * HH];  // [g][h] 32 KB
    int e = blockIdx.x;
    int m0 = blockIdx.y * 256 + threadIdx.x * 4;

    const float4* hh4 = (const float4*)g_Hh;
    for (int i = threadIdx.x; i < GG * HH / 4; i += 64)
        ((float4*)hs)[i] = hh4[(size_t)e * (GG * HH / 4) + i];
    __syncthreads();

    float acc[4][4] = {};
    const float4* w4 = (const float4*)(wo + (size_t)e * HH * MM);
#pragma unroll 8
    for (int h = 0; h < HH; h++) {
        float4 w = w4[(h * MM + m0) >> 2];
#pragma unroll
        for (int gg = 0; gg < 4; gg++) {
            float hv = hs[gg * HH + h];
            acc[gg][0] += hv * w.x;
            acc[gg][1] += hv * w.y;
            acc[gg][2] += hv * w.z;
            acc[gg][3] += hv * w.w;
        }
    }
#pragma unroll
    for (int gg = 0; gg < 4; gg++) {
        float4 v = make_float4(acc[gg][0], acc[gg][1], acc[gg][2], acc[gg][3]);
        *((float4*)(g_O + ((size_t)(e * GG + gg) * MM + m0))) = v;
    }
}

// ---------------------------------------------------------------------------
// K5: out[row][m] = 64 * sum_e gates[row][e] * O[e][g][m]
// grid (4 m-blocks of 256, 512 row-blocks of 16) x 256 thr; 4r x 4m per thread
// ---------------------------------------------------------------------------
__global__ __launch_bounds__(256) void k5_combine(float* __restrict__ out) {
    __shared__ float gsm[16 * 64];   // 4 KB
    __shared__ float osm[16 * 256];  // 16 KB (one 16-expert chunk)
    int m0 = blockIdx.x * 256;
    int row0 = blockIdx.y * 16;
    int g = row0 >> 11;  // 2048 rows per group, 16 | 2048 so block is g-pure
    int tx = threadIdx.x & 63;  // m (4 wide)
    int ty = threadIdx.x >> 6;  // row group (4 rows)

    for (int i = threadIdx.x; i < 16 * 16; i += 256)  // 16 rows x 16 float4
        ((float4*)gsm)[i] = ((const float4*)(g_gates + (size_t)row0 * EE))[i];

    float acc[4][4] = {};
    for (int ec = 0; ec < 4; ec++) {
        __syncthreads();
        for (int i = threadIdx.x; i < 16 * 64; i += 256) {  // 16 e x 64 float4
            int eI = i >> 6, c = i & 63;
            ((float4*)osm)[i] =
                ((const float4*)(g_O + (size_t)((ec * 16 + eI) * GG + g) * MM + m0))[c];
        }
        __syncthreads();
#pragma unroll
        for (int eI = 0; eI < 16; eI++) {
            float4 ov = ((float4*)osm)[eI * 64 + tx];
#pragma unroll
            for (int ii = 0; ii < 4; ii++) {
                float ge = gsm[(ty * 4 + ii) * 64 + ec * 16 + eI];
                acc[ii][0] += ge * ov.x;
                acc[ii][1] += ge * ov.y;
                acc[ii][2] += ge * ov.z;
                acc[ii][3] += ge * ov.w;
            }
        }
    }
#pragma unroll
    for (int ii = 0; ii < 4; ii++) {
        int row = row0 + ty * 4 + ii;
        float4 v = make_float4(acc[ii][0] * 64.f, acc[ii][1] * 64.f,
                               acc[ii][2] * 64.f, acc[ii][3] * 64.f);
        ((float4*)(out + (size_t)row * MM + m0))[tx] = v;
    }
}

// ---------------------------------------------------------------------------
extern "C" void kernel_launch(void* const* d_in, const int* in_sizes, int n_in,
                              void* d_out, int out_size) {
    const float* x  = (const float*)d_in[0];  // (8192, 1024)
    const float* wg = (const float*)d_in[1];  // (1024, 64)
    const float* wi = (const float*)d_in[2];  // (64, 1024, 2048)
    const float* wo = (const float*)d_in[3];  // (64, 2048, 1024)
    float* out = (float*)d_out;

    k1_gates<<<1024, 256>>>(x, wg);
    k2_dispatch<<<dim3(16, 4, 4), 256>>>(x);
    k3_ffn1<<<dim3(64, 4), 128>>>(wi);
    k4_ffn2<<<dim3(64, 4), 64>>>(wo);
    k5_combine<<<dim3(4, 512), 256>>>(out);
}

// round 4
// speedup vs baseline: 1.6591x; 1.6591x over previous
#include <cuda_runtime.h>

#define SS 2048
#define MM 1024
#define HH 2048
#define EE 64
#define GG 4

// Scratch (device globals; allocation-free)
__device__ float g_gates[GG * SS * EE];        // [row][e]                       (2 MB)
__device__ float g_Dpart[4 * EE * GG * MM];    // [sc][e][g][m] split-S partials (4 MB)
__device__ float g_Hpart[4 * EE * GG * HH];    // [mc][e][g][h] pre-ReLU partial (8 MB)
__device__ float g_Opart[8 * EE * GG * MM];    // [hc][e][g][m] partials         (8 MB)
__device__ float g_O[EE * GG * MM];            // [e][g][m]                      (1 MB)

// ---------------------------------------------------------------------------
// K1: gates[row][e] = sum_m x[row][m] * wg[m][e]
// ---------------------------------------------------------------------------
__global__ __launch_bounds__(256) void k1_gates(const float* __restrict__ x,
                                                const float* __restrict__ wg) {
    __shared__ float xs[8 * MM];  // 32 KB
    int row0 = blockIdx.x * 8;
    const float4* x4 = (const float4*)(x + (size_t)row0 * MM);
    float4* xs4 = (float4*)xs;
    for (int i = threadIdx.x; i < 8 * MM / 4; i += 256) xs4[i] = x4[i];
    __syncthreads();

    int e = threadIdx.x & 63;
    int rq = threadIdx.x >> 6;  // 0..3  (rows rq and rq+4)
    float acc0 = 0.f, acc1 = 0.f;
#pragma unroll 8
    for (int m = 0; m < MM; m++) {
        float w = __ldg(wg + m * EE + e);
        acc0 += xs[rq * MM + m] * w;
        acc1 += xs[(rq + 4) * MM + m] * w;
    }
    g_gates[(row0 + rq) * EE + e] = acc0;
    g_gates[(row0 + rq + 4) * EE + e] = acc1;
}

// ---------------------------------------------------------------------------
// K2: Dpart[sc][e][g][m] = sum_{s in chunk sc} gates[g,s,e] * x[g,s,m]
// ---------------------------------------------------------------------------
__global__ __launch_bounds__(256) void k2_dispatch(const float* __restrict__ x) {
    __shared__ float gs[64 * 64];   // [s][e] 16 KB
    __shared__ float xsm[64 * 64];  // [s][m] 16 KB
    int m0 = blockIdx.x * 64;
    int g  = blockIdx.y;
    int sc = blockIdx.z;
    int tx = threadIdx.x & 15;   // m group (4 wide)
    int ty = threadIdx.x >> 4;   // e group (4 wide)

    float acc[4][4] = {};
    for (int s0 = sc * 512; s0 < sc * 512 + 512; s0 += 64) {
        __syncthreads();
        for (int i = threadIdx.x; i < 64 * 16; i += 256) {
            int ss = i >> 4, c = i & 15;
            ((float4*)gs)[ss * 16 + c] =
                ((const float4*)(g_gates + (size_t)(g * SS + s0 + ss) * EE))[c];
            ((float4*)xsm)[ss * 16 + c] =
                ((const float4*)(x + (size_t)(g * SS + s0 + ss) * MM + m0))[c];
        }
        __syncthreads();
#pragma unroll 8
        for (int ss = 0; ss < 64; ss++) {
            float ge[4], xv[4];
#pragma unroll
            for (int j = 0; j < 4; j++) ge[j] = gs[ss * 64 + ty * 4 + j];
#pragma unroll
            for (int j = 0; j < 4; j++) xv[j] = xsm[ss * 64 + tx * 4 + j];
#pragma unroll
            for (int ii = 0; ii < 4; ii++)
#pragma unroll
                for (int jj = 0; jj < 4; jj++) acc[ii][jj] += ge[ii] * xv[jj];
        }
    }
#pragma unroll
    for (int ii = 0; ii < 4; ii++) {
        int ee = ty * 4 + ii;
        float4 v = make_float4(acc[ii][0], acc[ii][1], acc[ii][2], acc[ii][3]);
        *((float4*)(g_Dpart + (((sc * EE + ee) * GG + g) * MM + m0 + tx * 4))) = v;
    }
}

// ---------------------------------------------------------------------------
// K3: Hpart[mc][e][g][h] = sum_{m in chunk mc} D[e,g,m] * wi[e][m][h]
// grid (64 e, 2 h-halves, 4 m-chunks) x 256 thr. Streams wi (512 MB) once.
// ---------------------------------------------------------------------------
__global__ __launch_bounds__(256) void k3_ffn1(const float* __restrict__ wi) {
    __shared__ float ds[GG * 256];  // [g][m-local] 4 KB
    int e  = blockIdx.x;
    int hb = blockIdx.y;            // 0..1
    int mc = blockIdx.z;            // 0..3
    int h0 = hb * 1024 + threadIdx.x * 4;

    // assemble D[e][g][mc*256 .. +256) from split-S partials
    for (int i = threadIdx.x; i < GG * 256 / 4; i += 256) {  // 256 float4
        int g = i >> 6, c = i & 63;
        size_t base = ((size_t)e * GG + g) * MM + mc * 256 + c * 4;
        const float4 a = *(const float4*)(g_Dpart + (size_t)0 * EE * GG * MM + base);
        const float4 b = *(const float4*)(g_Dpart + (size_t)1 * EE * GG * MM + base);
        const float4 cc = *(const float4*)(g_Dpart + (size_t)2 * EE * GG * MM + base);
        const float4 d = *(const float4*)(g_Dpart + (size_t)3 * EE * GG * MM + base);
        ((float4*)ds)[i] = make_float4(a.x + b.x + cc.x + d.x, a.y + b.y + cc.y + d.y,
                                       a.z + b.z + cc.z + d.z, a.w + b.w + cc.w + d.w);
    }
    __syncthreads();

    float acc[4][4] = {};
    const float4* w4 = (const float4*)(wi + (size_t)e * MM * HH);
#pragma unroll 8
    for (int mi = 0; mi < 256; mi++) {
        int m = mc * 256 + mi;
        float4 w = w4[((size_t)m * HH + h0) >> 2];
#pragma unroll
        for (int g = 0; g < 4; g++) {
            float d = ds[g * 256 + mi];
            acc[g][0] += d * w.x;
            acc[g][1] += d * w.y;
            acc[g][2] += d * w.z;
            acc[g][3] += d * w.w;
        }
    }
#pragma unroll
    for (int g = 0; g < 4; g++) {
        float4 v = make_float4(acc[g][0], acc[g][1], acc[g][2], acc[g][3]);
        *((float4*)(g_Hpart + (((size_t)mc * EE + e) * GG + g) * HH + h0)) = v;
    }
}

// ---------------------------------------------------------------------------
// K4: Opart[hc][e][g][m] = sum_{h in chunk hc} relu(Hh[e,g,h]) * wo[e][h][m]
// grid (64 e, 8 h-chunks) x 256 thr. Streams wo (512 MB) once.
// ---------------------------------------------------------------------------
__global__ __launch_bounds__(256) void k4_ffn2(const float* __restrict__ wo) {
    __shared__ float hs[GG * 256];  // [g][h-local] 4 KB
    int e  = blockIdx.x;
    int hc = blockIdx.y;            // 0..7
    int m0 = threadIdx.x * 4;

    for (int i = threadIdx.x; i < GG * 256 / 4; i += 256) {  // 256 float4
        int g = i >> 6, c = i & 63;
        size_t base = ((size_t)e * GG + g) * HH + hc * 256 + c * 4;
        const float4 a = *(const float4*)(g_Hpart + (size_t)0 * EE * GG * HH + base);
        const float4 b = *(const float4*)(g_Hpart + (size_t)1 * EE * GG * HH + base);
        const float4 cc = *(const float4*)(g_Hpart + (size_t)2 * EE * GG * HH + base);
        const float4 d = *(const float4*)(g_Hpart + (size_t)3 * EE * GG * HH + base);
        ((float4*)hs)[i] = make_float4(fmaxf(a.x + b.x + cc.x + d.x, 0.f),
                                       fmaxf(a.y + b.y + cc.y + d.y, 0.f),
                                       fmaxf(a.z + b.z + cc.z + d.z, 0.f),
                                       fmaxf(a.w + b.w + cc.w + d.w, 0.f));
    }
    __syncthreads();

    float acc[4][4] = {};
    const float4* w4 = (const float4*)(wo + (size_t)e * HH * MM);
#pragma unroll 8
    for (int hi = 0; hi < 256; hi++) {
        int h = hc * 256 + hi;
        float4 w = w4[((size_t)h * MM + m0) >> 2];
#pragma unroll
        for (int g = 0; g < 4; g++) {
            float hv = hs[g * 256 + hi];
            acc[g][0] += hv * w.x;
            acc[g][1] += hv * w.y;
            acc[g][2] += hv * w.z;
            acc[g][3] += hv * w.w;
        }
    }
#pragma unroll
    for (int g = 0; g < 4; g++) {
        float4 v = make_float4(acc[g][0], acc[g][1], acc[g][2], acc[g][3]);
        *((float4*)(g_Opart + (((size_t)hc * EE + e) * GG + g) * MM + m0)) = v;
    }
}

// ---------------------------------------------------------------------------
// K4b: O = sum over 8 h-chunk partials. 65536 float4 elements total.
// grid 256 x 256 thr (one float4 per thread).
// ---------------------------------------------------------------------------
__global__ __launch_bounds__(256) void k4b_reduce() {
    int idx = blockIdx.x * 256 + threadIdx.x;  // float4 index, 65536 total
    const float4* p = (const float4*)g_Opart;
    float4 s = p[idx];
#pragma unroll
    for (int hc = 1; hc < 8; hc++) {
        float4 v = p[(size_t)hc * (EE * GG * MM / 4) + idx];
        s.x += v.x; s.y += v.y; s.z += v.z; s.w += v.w;
    }
    ((float4*)g_O)[idx] = s;
}

// ---------------------------------------------------------------------------
// K5: out[row][m] = 64 * sum_e gates[row][e] * O[e][g][m]
// ---------------------------------------------------------------------------
__global__ __launch_bounds__(256) void k5_combine(float* __restrict__ out) {
    __shared__ float gsm[16 * 64];   // 4 KB
    __shared__ float osm[16 * 256];  // 16 KB
    int m0 = blockIdx.x * 256;
    int row0 = blockIdx.y * 16;
    int g = row0 >> 11;
    int tx = threadIdx.x & 63;  // m (4 wide)
    int ty = threadIdx.x >> 6;  // row group (4 rows)

    for (int i = threadIdx.x; i < 16 * 16; i += 256)
        ((float4*)gsm)[i] = ((const float4*)(g_gates + (size_t)row0 * EE))[i];

    float acc[4][4] = {};
    for (int ec = 0; ec < 4; ec++) {
        __syncthreads();
        for (int i = threadIdx.x; i < 16 * 64; i += 256) {
            int eI = i >> 6, c = i & 63;
            ((float4*)osm)[i] =
                ((const float4*)(g_O + (size_t)((ec * 16 + eI) * GG + g) * MM + m0))[c];
        }
        __syncthreads();
#pragma unroll
        for (int eI = 0; eI < 16; eI++) {
            float4 ov = ((float4*)osm)[eI * 64 + tx];
#pragma unroll
            for (int ii = 0; ii < 4; ii++) {
                float ge = gsm[(ty * 4 + ii) * 64 + ec * 16 + eI];
                acc[ii][0] += ge * ov.x;
                acc[ii][1] += ge * ov.y;
                acc[ii][2] += ge * ov.z;
                acc[ii][3] += ge * ov.w;
            }
        }
    }
#pragma unroll
    for (int ii = 0; ii < 4; ii++) {
        int row = row0 + ty * 4 + ii;
        float4 v = make_float4(acc[ii][0] * 64.f, acc[ii][1] * 64.f,
                               acc[ii][2] * 64.f, acc[ii][3] * 64.f);
        ((float4*)(out + (size_t)row * MM + m0))[tx] = v;
    }
}

// ---------------------------------------------------------------------------
extern "C" void kernel_launch(void* const* d_in, const int* in_sizes, int n_in,
                              void* d_out, int out_size) {
    const float* x  = (const float*)d_in[0];  // (8192, 1024)
    const float* wg = (const float*)d_in[1];  // (1024, 64)
    const float* wi = (const float*)d_in[2];  // (64, 1024, 2048)
    const float* wo = (const float*)d_in[3];  // (64, 2048, 1024)
    float* out = (float*)d_out;

    k1_gates<<<1024, 256>>>(x, wg);
    k2_dispatch<<<dim3(16, 4, 4), 256>>>(x);
    k3_ffn1<<<dim3(64, 2, 4), 256>>>(wi);
    k4_ffn2<<<dim3(64, 8), 256>>>(wo);
    k4b_reduce<<<256, 256>>>();
    k5_combine<<<dim3(4, 512), 256>>>(out);
}

// round 5
// speedup vs baseline: 1.9008x; 1.1456x over previous
#include <cuda_runtime.h>

#define SS 2048
#define MM 1024
#define HH 2048
#define EE 64
#define GG 4

typedef unsigned long long u64;

// Scratch (device globals; allocation-free)
__device__ float g_Gpart[4 * GG * SS * EE];    // [kc][row][e] gate partials     (8 MB)
__device__ float g_gates[GG * SS * EE];        // [row][e]                       (2 MB)
__device__ float g_Dpart[4 * EE * GG * MM];    // [sc][e][g][m] split-S partials (4 MB)
__device__ float g_Hpart[8 * EE * GG * HH];    // [mc][e][g][h] pre-ReLU partial (16 MB)
__device__ float g_Opart[16 * EE * GG * MM];   // [hc][e][g][m] partials         (16 MB)
__device__ float g_O[EE * GG * MM];            // [e][g][m]                      (1 MB)

// ---- packed fp32x2 helpers (Blackwell FFMA2; only reachable via PTX) ------
__device__ __forceinline__ void ffma2(u64& d, u64 a, u64 b) {
    asm("fma.rn.f32x2 %0, %1, %2, %0;" : "+l"(d) : "l"(a), "l"(b));
}
__device__ __forceinline__ u64 dup2(float x) {
    u64 r; asm("mov.b64 %0, {%1, %1};" : "=l"(r) : "f"(x)); return r;
}
__device__ __forceinline__ float2 unpack2(u64 v) {
    float2 r; asm("mov.b64 {%0, %1}, %2;" : "=f"(r.x), "=f"(r.y) : "l"(v)); return r;
}

// ---------------------------------------------------------------------------
// K1: Gpart[kc][row][e] = sum_{m in kc chunk} x[row][m] * wg[m][e]
// grid (128 row-tiles of 64, 4 kc of 256) x 256 thr; thread = 4r x 4e (FFMA2)
// ---------------------------------------------------------------------------
__global__ __launch_bounds__(256) void k1_gates(const float* __restrict__ x,
                                                const float* __restrict__ wg) {
    __shared__ float xs[64 * 32];  // [r][k] 8 KB
    __shared__ float ws[32 * 64];  // [k][e] 8 KB
    int r0 = blockIdx.x * 64;
    int kc = blockIdx.y;  // 0..3
    int tx = threadIdx.x & 15;   // e group (4 wide)
    int ty = threadIdx.x >> 4;   // r group (4 wide)

    u64 acc[4][2] = {};  // [r][e-pair]; f32 zero bits are 0
    for (int ks = 0; ks < 8; ks++) {
        int kb = kc * 256 + ks * 32;
        __syncthreads();
        for (int i = threadIdx.x; i < 2048; i += 256) {
            int r = i >> 5, k = i & 31;
            xs[r * 32 + k] = x[(size_t)(r0 + r) * MM + kb + k];
        }
        for (int i = threadIdx.x; i < 2048; i += 256) {
            int k = i >> 6, e = i & 63;
            ws[k * 64 + e] = wg[(size_t)(kb + k) * EE + e];
        }
        __syncthreads();
#pragma unroll
        for (int k = 0; k < 32; k++) {
            u64 w01 = *(const u64*)(ws + k * 64 + tx * 4);
            u64 w23 = *(const u64*)(ws + k * 64 + tx * 4 + 2);
#pragma unroll
            for (int ii = 0; ii < 4; ii++) {
                u64 xd = dup2(xs[(ty * 4 + ii) * 32 + k]);
                ffma2(acc[ii][0], xd, w01);
                ffma2(acc[ii][1], xd, w23);
            }
        }
    }
#pragma unroll
    for (int ii = 0; ii < 4; ii++) {
        float2 a = unpack2(acc[ii][0]), b = unpack2(acc[ii][1]);
        float4 v = make_float4(a.x, a.y, b.x, b.y);
        *((float4*)(g_Gpart + ((size_t)kc * GG * SS * EE) +
                    (size_t)(r0 + ty * 4 + ii) * EE + tx * 4)) = v;
    }
}

// K1b: gates = sum of 4 K partials. 131072 float4 -> 512 blocks x 256 thr.
__global__ __launch_bounds__(256) void k1b_reduce() {
    int idx = blockIdx.x * 256 + threadIdx.x;  // float4 index
    const float4* p = (const float4*)g_Gpart;
    float4 s = p[idx];
#pragma unroll
    for (int kc = 1; kc < 4; kc++) {
        float4 v = p[(size_t)kc * (GG * SS * EE / 4) + idx];
        s.x += v.x; s.y += v.y; s.z += v.z; s.w += v.w;
    }
    ((float4*)g_gates)[idx] = s;
}

// ---------------------------------------------------------------------------
// K2: Dpart[sc][e][g][m] = sum_{s in chunk sc} gates[g,s,e] * x[g,s,m]
// grid (16 m-tiles, 4 g, 4 s-chunks) x 256 thr; thread = 4e x 4m (FFMA2)
// ---------------------------------------------------------------------------
__global__ __launch_bounds__(256) void k2_dispatch(const float* __restrict__ x) {
    __shared__ float gs[64 * 64];   // [s][e] 16 KB
    __shared__ float xsm[64 * 64];  // [s][m] 16 KB
    int m0 = blockIdx.x * 64;
    int g  = blockIdx.y;
    int sc = blockIdx.z;
    int tx = threadIdx.x & 15;   // m group (4 wide)
    int ty = threadIdx.x >> 4;   // e group (4 wide)

    u64 acc[4][2] = {};  // [e][m-pair]
    for (int s0 = sc * 512; s0 < sc * 512 + 512; s0 += 64) {
        __syncthreads();
        for (int i = threadIdx.x; i < 64 * 16; i += 256) {
            int ss = i >> 4, c = i & 15;
            ((float4*)gs)[ss * 16 + c] =
                ((const float4*)(g_gates + (size_t)(g * SS + s0 + ss) * EE))[c];
            ((float4*)xsm)[ss * 16 + c] =
                ((const float4*)(x + (size_t)(g * SS + s0 + ss) * MM + m0))[c];
        }
        __syncthreads();
#pragma unroll 8
        for (int ss = 0; ss < 64; ss++) {
            float4 ge = *(const float4*)(gs + ss * 64 + ty * 4);
            u64 x01 = *(const u64*)(xsm + ss * 64 + tx * 4);
            u64 x23 = *(const u64*)(xsm + ss * 64 + tx * 4 + 2);
            u64 g0 = dup2(ge.x), g1 = dup2(ge.y), g2 = dup2(ge.z), g3 = dup2(ge.w);
            ffma2(acc[0][0], g0, x01); ffma2(acc[0][1], g0, x23);
            ffma2(acc[1][0], g1, x01); ffma2(acc[1][1], g1, x23);
            ffma2(acc[2][0], g2, x01); ffma2(acc[2][1], g2, x23);
            ffma2(acc[3][0], g3, x01); ffma2(acc[3][1], g3, x23);
        }
    }
#pragma unroll
    for (int ii = 0; ii < 4; ii++) {
        int ee = ty * 4 + ii;
        float2 a = unpack2(acc[ii][0]), b = unpack2(acc[ii][1]);
        float4 v = make_float4(a.x, a.y, b.x, b.y);
        *((float4*)(g_Dpart + (((size_t)sc * EE + ee) * GG + g) * MM + m0 + tx * 4)) = v;
    }
}

// ---------------------------------------------------------------------------
// K3: Hpart[mc][e][g][h] = sum_{m in chunk mc(128)} D[e,g,m] * wi[e][m][h]
// grid (64 e, 2 h-halves, 8 m-chunks) = 1024 blocks x 256 thr. Streams wi once.
// ---------------------------------------------------------------------------
__global__ __launch_bounds__(256) void k3_ffn1(const float* __restrict__ wi) {
    __shared__ float ds[GG * 128];  // [g][m-local] 2 KB
    int e  = blockIdx.x;
    int hb = blockIdx.y;            // 0..1
    int mc = blockIdx.z;            // 0..7
    int h0 = hb * 1024 + threadIdx.x * 4;

    for (int i = threadIdx.x; i < GG * 128 / 4; i += 256) {  // 128 float4
        int g = i >> 5, c = i & 31;
        size_t base = ((size_t)e * GG + g) * MM + mc * 128 + c * 4;
        const float4 a = *(const float4*)(g_Dpart + (size_t)0 * EE * GG * MM + base);
        const float4 b = *(const float4*)(g_Dpart + (size_t)1 * EE * GG * MM + base);
        const float4 cc = *(const float4*)(g_Dpart + (size_t)2 * EE * GG * MM + base);
        const float4 d = *(const float4*)(g_Dpart + (size_t)3 * EE * GG * MM + base);
        ((float4*)ds)[i] = make_float4(a.x + b.x + cc.x + d.x, a.y + b.y + cc.y + d.y,
                                       a.z + b.z + cc.z + d.z, a.w + b.w + cc.w + d.w);
    }
    __syncthreads();

    float acc[4][4] = {};
    const float4* w4 = (const float4*)(wi + (size_t)e * MM * HH);
#pragma unroll 8
    for (int mi = 0; mi < 128; mi++) {
        int m = mc * 128 + mi;
        float4 w = w4[((size_t)m * HH + h0) >> 2];
#pragma unroll
        for (int g = 0; g < 4; g++) {
            float d = ds[g * 128 + mi];
            acc[g][0] += d * w.x;
            acc[g][1] += d * w.y;
            acc[g][2] += d * w.z;
            acc[g][3] += d * w.w;
        }
    }
#pragma unroll
    for (int g = 0; g < 4; g++) {
        float4 v = make_float4(acc[g][0], acc[g][1], acc[g][2], acc[g][3]);
        *((float4*)(g_Hpart + (((size_t)mc * EE + e) * GG + g) * HH + h0)) = v;
    }
}

// ---------------------------------------------------------------------------
// K4: Opart[hc][e][g][m] = sum_{h in chunk hc(128)} relu(Hh[e,g,h]) * wo[e][h][m]
// grid (64 e, 16 h-chunks) = 1024 blocks x 256 thr. Streams wo once.
// Hh chunk = relu(sum of 8 K3 partials), assembled at SMEM-fill time.
// ---------------------------------------------------------------------------
__global__ __launch_bounds__(256) void k4_ffn2(const float* __restrict__ wo) {
    __shared__ float hs[GG * 128];  // [g][h-local] 2 KB
    int e  = blockIdx.x;
    int hc = blockIdx.y;            // 0..15
    int m0 = threadIdx.x * 4;

    for (int i = threadIdx.x; i < GG * 128 / 4; i += 256) {  // 128 float4
        int g = i >> 5, c = i & 31;
        size_t base = ((size_t)e * GG + g) * HH + hc * 128 + c * 4;
        float4 s = *(const float4*)(g_Hpart + base);
#pragma unroll
        for (int mc = 1; mc < 8; mc++) {
            const float4 v = *(const float4*)(g_Hpart + (size_t)mc * EE * GG * HH + base);
            s.x += v.x; s.y += v.y; s.z += v.z; s.w += v.w;
        }
        ((float4*)hs)[i] = make_float4(fmaxf(s.x, 0.f), fmaxf(s.y, 0.f),
                                       fmaxf(s.z, 0.f), fmaxf(s.w, 0.f));
    }
    __syncthreads();

    float acc[4][4] = {};
    const float4* w4 = (const float4*)(wo + (size_t)e * HH * MM);
#pragma unroll 8
    for (int hi = 0; hi < 128; hi++) {
        int h = hc * 128 + hi;
        float4 w = w4[((size_t)h * MM + m0) >> 2];
#pragma unroll
        for (int g = 0; g < 4; g++) {
            float hv = hs[g * 128 + hi];
            acc[g][0] += hv * w.x;
            acc[g][1] += hv * w.y;
            acc[g][2] += hv * w.z;
            acc[g][3] += hv * w.w;
        }
    }
#pragma unroll
    for (int g = 0; g < 4; g++) {
        float4 v = make_float4(acc[g][0], acc[g][1], acc[g][2], acc[g][3]);
        *((float4*)(g_Opart + (((size_t)hc * EE + e) * GG + g) * MM + m0)) = v;
    }
}

// ---------------------------------------------------------------------------
// K4b: O = sum over 16 h-chunk partials. 65536 float4 -> 256 blocks x 256 thr.
// ---------------------------------------------------------------------------
__global__ __launch_bounds__(256) void k4b_reduce() {
    int idx = blockIdx.x * 256 + threadIdx.x;  // float4 index, 65536 total
    const float4* p = (const float4*)g_Opart;
    float4 s = p[idx];
#pragma unroll
    for (int hc = 1; hc < 16; hc++) {
        float4 v = p[(size_t)hc * (EE * GG * MM / 4) + idx];
        s.x += v.x; s.y += v.y; s.z += v.z; s.w += v.w;
    }
    ((float4*)g_O)[idx] = s;
}

// ---------------------------------------------------------------------------
// K5: out[row][m] = 64 * sum_e gates[row][e] * O[e][g][m]   (FFMA2)
// grid (4 m-blocks of 256, 512 row-blocks of 16) x 256 thr; 4r x 4m per thread
// ---------------------------------------------------------------------------
__global__ __launch_bounds__(256) void k5_combine(float* __restrict__ out) {
    __shared__ float gsm[16 * 64];   // 4 KB
    __shared__ float osm[16 * 256];  // 16 KB
    int m0 = blockIdx.x * 256;
    int row0 = blockIdx.y * 16;
    int g = row0 >> 11;
    int tx = threadIdx.x & 63;  // m (4 wide)
    int ty = threadIdx.x >> 6;  // row group (4 rows)

    for (int i = threadIdx.x; i < 16 * 16; i += 256)
        ((float4*)gsm)[i] = ((const float4*)(g_gates + (size_t)row0 * EE))[i];

    u64 acc[4][2] = {};  // [r][m-pair]
    for (int ec = 0; ec < 4; ec++) {
        __syncthreads();
        for (int i = threadIdx.x; i < 16 * 64; i += 256) {
            int eI = i >> 6, c = i & 63;
            ((float4*)osm)[i] =
                ((const float4*)(g_O + (size_t)((ec * 16 + eI) * GG + g) * MM + m0))[c];
        }
        __syncthreads();
#pragma unroll
        for (int eI = 0; eI < 16; eI++) {
            u64 o01 = *(const u64*)(osm + eI * 256 + tx * 4);
            u64 o23 = *(const u64*)(osm + eI * 256 + tx * 4 + 2);
#pragma unroll
            for (int ii = 0; ii < 4; ii++) {
                u64 gd = dup2(gsm[(ty * 4 + ii) * 64 + ec * 16 + eI]);
                ffma2(acc[ii][0], gd, o01);
                ffma2(acc[ii][1], gd, o23);
            }
        }
    }
#pragma unroll
    for (int ii = 0; ii < 4; ii++) {
        int row = row0 + ty * 4 + ii;
        float2 a = unpack2(acc[ii][0]), b = unpack2(acc[ii][1]);
        float4 v = make_float4(a.x * 64.f, a.y * 64.f, b.x * 64.f, b.y * 64.f);
        ((float4*)(out + (size_t)row * MM + m0))[tx] = v;
    }
}

// ---------------------------------------------------------------------------
extern "C" void kernel_launch(void* const* d_in, const int* in_sizes, int n_in,
                              void* d_out, int out_size) {
    const float* x  = (const float*)d_in[0];  // (8192, 1024)
    const float* wg = (const float*)d_in[1];  // (1024, 64)
    const float* wi = (const float*)d_in[2];  // (64, 1024, 2048)
    const float* wo = (const float*)d_in[3];  // (64, 2048, 1024)
    float* out = (float*)d_out;

    k1_gates<<<dim3(128, 4), 256>>>(x, wg);
    k1b_reduce<<<512, 256>>>();
    k2_dispatch<<<dim3(16, 4, 4), 256>>>(x);
    k3_ffn1<<<dim3(64, 2, 8), 256>>>(wi);
    k4_ffn2<<<dim3(64, 16), 256>>>(wo);
    k4b_reduce<<<256, 256>>>();
    k5_combine<<<dim3(4, 512), 256>>>(out);
}